// round 3
// baseline (speedup 1.0000x reference)
#include <cuda_runtime.h>
#include <cuda_bf16.h>

// S1 gated delta-rule recurrent cell, single step.
// Shapes: B=128, H=16, Dk=Dv=128.
// Inputs (metadata order): q[BH*128], k[BH*128], v[BH*128], g[BH], beta[BH],
//                          last_recurrent_state[BH*128*128]
// Output: concat(out[BH*128], new_state[BH*128*128]) as float32.
//
// Math per (b,h):
//   decay = exp(g); S = S_in * decay
//   kv_mem[v] = sum_k S[k][v] * k[k]
//   delta[v]  = (v[v] - kv_mem[v]) * beta
//   S[k][v]  += k[k] * delta[v]
//   out[v]    = sum_k S[k][v] * q[k]
//
// One CTA per (b,h). 256 threads: t = v4 + 32*kc. v4 in [0,32) owns 4
// consecutive v columns (one float4); kc in [0,8) owns 16 k rows. Each
// thread keeps its 16-float4 state slice in REGISTERS between the two
// passes: state is read from DRAM exactly once and written exactly once
// (272 MB total traffic -> HBM roofline ~43 us).

#define DK 128
#define DV 128
#define BH 2048              // B*H
#define OUT_VEC_ELEMS (BH * DV)          // 262144

__global__ __launch_bounds__(256)
void s1_cell_kernel(const float* __restrict__ q_,
                    const float* __restrict__ k_,
                    const float* __restrict__ v_,
                    const float* __restrict__ g_,
                    const float* __restrict__ beta_,
                    const float* __restrict__ state_in,
                    float* __restrict__ out_all)
{
    const int bh = blockIdx.x;
    const int t  = threadIdx.x;
    const int v4 = t & 31;        // float4 column group: columns [4*v4, 4*v4+4)
    const int kc = t >> 5;        // k-chunk: rows [16*kc, 16*kc+16)

    const float4* __restrict__ S_in4 =
        reinterpret_cast<const float4*>(state_in + (size_t)bh * (DK * DV));
    float4* __restrict__ S_out4 =
        reinterpret_cast<float4*>(out_all + OUT_VEC_ELEMS + (size_t)bh * (DK * DV));
    float4* __restrict__ out4 =
        reinterpret_cast<float4*>(out_all + (size_t)bh * DV);

    __shared__ float  ks[DK];
    __shared__ float  qs[DK];
    __shared__ float4 red[8][32];    // cross-kc reduction buffer

    // Load per-(b,h) vectors into shared.
    if (t < DK) {
        ks[t] = k_[bh * DK + t];
        qs[t] = q_[bh * DK + t];
    }
    const float decay = expf(g_[bh]);
    const float beta  = beta_[bh];

    __syncthreads();

    // ---- Pass 1: batch-load the 16-row state slice (keeps 16 LDG.128 in
    // flight), then decay + accumulate kv partial.
    float4 s[16];
#pragma unroll
    for (int i = 0; i < 16; i++) {
        s[i] = S_in4[(kc * 16 + i) * 32 + v4];
    }
    float4 kv = make_float4(0.f, 0.f, 0.f, 0.f);
#pragma unroll
    for (int i = 0; i < 16; i++) {
        float4 x = s[i];
        x.x *= decay; x.y *= decay; x.z *= decay; x.w *= decay;
        s[i] = x;
        const float kk = ks[kc * 16 + i];
        kv.x = fmaf(x.x, kk, kv.x);
        kv.y = fmaf(x.y, kk, kv.y);
        kv.z = fmaf(x.z, kk, kv.z);
        kv.w = fmaf(x.w, kk, kv.w);
    }
    red[kc][v4] = kv;
    __syncthreads();

    // ---- Every thread reduces kv over the 8 k-chunks and forms delta
    // (redundant compute, but removes a barrier + broadcast round-trip).
    float4 acc = red[0][v4];
#pragma unroll
    for (int j = 1; j < 8; j++) {
        const float4 r = red[j][v4];
        acc.x += r.x; acc.y += r.y; acc.z += r.z; acc.w += r.w;
    }
    const float4 vv = reinterpret_cast<const float4*>(v_ + bh * DV)[v4];
    float4 d4;
    d4.x = (vv.x - acc.x) * beta;
    d4.y = (vv.y - acc.y) * beta;
    d4.z = (vv.z - acc.z) * beta;
    d4.w = (vv.w - acc.w) * beta;

    // ---- Pass 2: rank-1 update from registers, write state, accumulate out.
    float4 o = make_float4(0.f, 0.f, 0.f, 0.f);
#pragma unroll
    for (int i = 0; i < 16; i++) {
        const int krow = kc * 16 + i;
        const float kk = ks[krow];
        const float qq = qs[krow];
        float4 x = s[i];
        x.x = fmaf(kk, d4.x, x.x);
        x.y = fmaf(kk, d4.y, x.y);
        x.z = fmaf(kk, d4.z, x.z);
        x.w = fmaf(kk, d4.w, x.w);
        S_out4[krow * 32 + v4] = x;
        o.x = fmaf(x.x, qq, o.x);
        o.y = fmaf(x.y, qq, o.y);
        o.z = fmaf(x.z, qq, o.z);
        o.w = fmaf(x.w, qq, o.w);
    }
    __syncthreads();   // all reads of red (kv reduction) done before overwrite
    red[kc][v4] = o;
    __syncthreads();

    // ---- Reduce out over k-chunks, write output vector (warp 0 only).
    if (kc == 0) {
        float4 oacc = red[0][v4];
#pragma unroll
        for (int j = 1; j < 8; j++) {
            const float4 r = red[j][v4];
            oacc.x += r.x; oacc.y += r.y; oacc.z += r.z; oacc.w += r.w;
        }
        out4[v4] = oacc;
    }
}

extern "C" void kernel_launch(void* const* d_in, const int* in_sizes, int n_in,
                              void* d_out, int out_size)
{
    const float* q    = (const float*)d_in[0];
    const float* k    = (const float*)d_in[1];
    const float* v    = (const float*)d_in[2];
    const float* g    = (const float*)d_in[3];
    const float* beta = (const float*)d_in[4];
    const float* st   = (const float*)d_in[5];
    float* out = (float*)d_out;

    s1_cell_kernel<<<BH, 256>>>(q, k, v, g, beta, st, out);
}